// round 4
// baseline (speedup 1.0000x reference)
#include <cuda_runtime.h>
#include <cuda_bf16.h>
#include <math.h>
#include <stdint.h>

#define NN 25000
#define EE 400000
#define TOTE (EE + NN)
#define HD 384
#define DH 128

// ---------------- device scratch ----------------
__device__ __align__(16) float g_xlr[NN * 2 * HD];   // [N,768]: cols 0..383 xl, 384..767 xr
__device__ __align__(16) float g_xin[NN * HD];
__device__ __align__(16) float g_h2[NN * HD];
__device__ __align__(16) float g_h[NN * DH];
__device__ __align__(16) float g_y[NN * DH];
__device__ int   g_deg[NN];
__device__ int   g_rowptr[NN + 1];
__device__ int   g_fill[NN];
__device__ int   g_srcs[TOTE];
__device__ float g_bnsum[DH];
__device__ float g_bnsq[DH];
// bf16 split buffers
__device__ __align__(16) __nv_bfloat16 g_sxh[NN * DH];   // x / h split (K=128 A)
__device__ __align__(16) __nv_bfloat16 g_sxl[NN * DH];
__device__ __align__(16) __nv_bfloat16 g_sah[NN * HD];   // xin split (K=384 A)
__device__ __align__(16) __nv_bfloat16 g_sal[NN * HD];
__device__ __align__(16) __nv_bfloat16 g_sch[NN * HD];   // h2 split (K=384 A)
__device__ __align__(16) __nv_bfloat16 g_scl[NN * HD];
__device__ __align__(16) __nv_bfloat16 g_wth[98304];     // transposed weight [N,K] bf16
__device__ __align__(16) __nv_bfloat16 g_wtl[98304];
__device__ float g_bcat[2 * HD];

// ---------------- small helpers ----------------
__device__ __forceinline__ float4 f4add(float4 a, float4 b) {
    return make_float4(a.x + b.x, a.y + b.y, a.z + b.z, a.w + b.w);
}
__device__ __forceinline__ float4 f4scale(float4 a, float s) {
    return make_float4(a.x * s, a.y * s, a.z * s, a.w * s);
}
__device__ __forceinline__ float4 f4fma(float4 a, float s, float4 c) {
    return make_float4(fmaf(a.x, s, c.x), fmaf(a.y, s, c.y),
                       fmaf(a.z, s, c.z), fmaf(a.w, s, c.w));
}
__device__ __forceinline__ float4 f4lrelu(float4 v) {
    const float ns = 0.2f;
    return make_float4(v.x > 0.f ? v.x : ns * v.x,
                       v.y > 0.f ? v.y : ns * v.y,
                       v.z > 0.f ? v.z : ns * v.z,
                       v.w > 0.f ? v.w : ns * v.w);
}
__device__ __forceinline__ float f4dot(float4 a, float4 b) {
    return fmaf(a.x, b.x, fmaf(a.y, b.y, fmaf(a.z, b.z, a.w * b.w)));
}

__device__ __forceinline__ void mma16816(float& c0, float& c1, float& c2, float& c3,
                                         uint32_t a0, uint32_t a1, uint32_t a2,
                                         uint32_t a3, uint32_t b0, uint32_t b1) {
    asm volatile(
        "mma.sync.aligned.m16n8k16.row.col.f32.bf16.bf16.f32 "
        "{%0,%1,%2,%3}, {%4,%5,%6,%7}, {%8,%9}, {%0,%1,%2,%3};"
        : "+f"(c0), "+f"(c1), "+f"(c2), "+f"(c3)
        : "r"(a0), "r"(a1), "r"(a2), "r"(a3), "r"(b0), "r"(b1));
}

// ---------------- CSR build ----------------
__global__ void set_int_kernel(int* p, int n, int v) {
    int i = blockIdx.x * blockDim.x + threadIdx.x;
    if (i < n) p[i] = v;
}

__global__ void hist_kernel(const int* __restrict__ ei, int* __restrict__ deg) {
    int i = blockIdx.x * blockDim.x + threadIdx.x;
    if (i < EE) {
        int d = ei[EE + i];
        if (d >= 0 && d < NN) atomicAdd(&deg[d], 1);
    }
}

__global__ void scan_kernel(const int* __restrict__ deg, int* __restrict__ rowptr,
                            int* __restrict__ fill) {
    __shared__ int sh[1024];
    const int CH = 25;
    int t = threadIdx.x;
    int start = t * CH;
    int end = start + CH;
    if (start > NN) start = NN;
    if (end > NN) end = NN;
    int s = 0;
    for (int i = start; i < end; i++) s += deg[i];
    sh[t] = s;
    __syncthreads();
    for (int o = 1; o < 1024; o <<= 1) {
        int v = (t >= o) ? sh[t - o] : 0;
        __syncthreads();
        sh[t] += v;
        __syncthreads();
    }
    int off = (t == 0) ? 0 : sh[t - 1];
    for (int i = start; i < end; i++) {
        rowptr[i] = off;
        fill[i] = off;
        off += deg[i];
    }
    if (t == 1023) rowptr[NN] = sh[1023];
}

__global__ void scatter_kernel(const int* __restrict__ ei, int* __restrict__ fill,
                               int* __restrict__ srcs) {
    int i = blockIdx.x * blockDim.x + threadIdx.x;
    if (i >= TOTE) return;
    int s, d;
    if (i < EE) {
        s = ei[i];
        d = ei[EE + i];
    } else {
        s = d = i - EE;
    }
    if (s < 0 || s >= NN || d < 0 || d >= NN) return;
    int pos = atomicAdd(&fill[d], 1);
    srcs[pos] = s;
}

// ---------------- fp32 -> bf16 split kernels ----------------
__global__ void split_kernel(const float* __restrict__ in, __nv_bfloat16* __restrict__ hi,
                             __nv_bfloat16* __restrict__ lo, int n) {
    int i = blockIdx.x * blockDim.x + threadIdx.x;
    if (i >= n) return;
    float v = in[i];
    __nv_bfloat16 h = __float2bfloat16(v);
    hi[i] = h;
    lo[i] = __float2bfloat16(v - __bfloat162float(h));
}

// W [K,N] row-major -> Wt [N,K] bf16 split
__global__ void tsplit_kernel(const float* __restrict__ W, __nv_bfloat16* __restrict__ th,
                              __nv_bfloat16* __restrict__ tl, int K, int N) {
    int i = blockIdx.x * blockDim.x + threadIdx.x;
    if (i >= K * N) return;
    int k = i / N;
    int n = i % N;
    float v = W[i];
    __nv_bfloat16 h = __float2bfloat16(v);
    th[(size_t)n * K + k] = h;
    tl[(size_t)n * K + k] = __float2bfloat16(v - __bfloat162float(h));
}

__global__ void bcat_kernel(const float* __restrict__ a, const float* __restrict__ b,
                            float* __restrict__ o) {
    int i = threadIdx.x + blockIdx.x * blockDim.x;
    if (i < HD) o[i] = a[i];
    else if (i < 2 * HD) o[i] = b[i - HD];
}

// ---------------- HMMA bf16 split-2 GEMM ----------------
// C[M,N] = (Ah+Al)@(Bh+Bl)^T (+bias)(+Cin); A [M,K] bf16, B [N,K] bf16.
// BM=128 BN=64 BK=32, 256 threads (8 warps, 4x2 m,n), warp tile 32x32.
// smem stride 20 words (80B rows): conflict-free fragment reads.
#define ASTR 20
__global__ void __launch_bounds__(256) gemm_mma_kernel(
    const __nv_bfloat16* __restrict__ Ah, const __nv_bfloat16* __restrict__ Al,
    const __nv_bfloat16* __restrict__ Bh, const __nv_bfloat16* __restrict__ Bl,
    const float* __restrict__ bias, const float* __restrict__ Cin,
    float* __restrict__ C, int M, int N, int K) {
    __shared__ uint32_t sAh[128 * ASTR], sAl[128 * ASTR];
    __shared__ uint32_t sBh[64 * ASTR], sBl[64 * ASTR];

    int tid = threadIdx.x;
    int wid = tid >> 5;
    int lane = tid & 31;
    int grp = lane >> 2;       // 0..7
    int tig = lane & 3;        // 0..3
    int wm = wid & 3;          // 4 warps over M (32 rows each)
    int wn = wid >> 2;         // 2 warps over N (32 cols each)
    int bm = blockIdx.y * 128;
    int bn = blockIdx.x * 64;

    float c[2][4][4];
#pragma unroll
    for (int i = 0; i < 2; i++)
#pragma unroll
        for (int j = 0; j < 4; j++)
#pragma unroll
            for (int q = 0; q < 4; q++) c[i][j][q] = 0.f;

    int nchunks = K >> 5;
    for (int kc = 0; kc < nchunks; kc++) {
        // load A tiles: 128 rows x 32 bf16 = 512 uint4; 2 per thread
#pragma unroll
        for (int l = 0; l < 2; l++) {
            int id = tid + l * 256;
            int r = id >> 2;
            int q = id & 3;
            int grow = bm + r;
            uint4 vh = make_uint4(0, 0, 0, 0), vl = vh;
            if (grow < M) {
                vh = *(const uint4*)(Ah + (size_t)grow * K + kc * 32 + q * 8);
                vl = *(const uint4*)(Al + (size_t)grow * K + kc * 32 + q * 8);
            }
            int off = r * ASTR + q * 4;
            *(uint2*)&sAh[off] = make_uint2(vh.x, vh.y);
            *(uint2*)&sAh[off + 2] = make_uint2(vh.z, vh.w);
            *(uint2*)&sAl[off] = make_uint2(vl.x, vl.y);
            *(uint2*)&sAl[off + 2] = make_uint2(vl.z, vl.w);
        }
        // load B tiles: 64 rows x 32 bf16 = 256 uint4; 1 per thread
        {
            int r = tid >> 2;
            int q = tid & 3;
            int grow = bn + r;
            uint4 vh = *(const uint4*)(Bh + (size_t)grow * K + kc * 32 + q * 8);
            uint4 vl = *(const uint4*)(Bl + (size_t)grow * K + kc * 32 + q * 8);
            int off = r * ASTR + q * 4;
            *(uint2*)&sBh[off] = make_uint2(vh.x, vh.y);
            *(uint2*)&sBh[off + 2] = make_uint2(vh.z, vh.w);
            *(uint2*)&sBl[off] = make_uint2(vl.x, vl.y);
            *(uint2*)&sBl[off + 2] = make_uint2(vl.z, vl.w);
        }
        __syncthreads();

#pragma unroll
        for (int pass = 0; pass < 3; pass++) {
            const uint32_t* Ap = (pass == 1) ? sAl : sAh;
            const uint32_t* Bp = (pass == 2) ? sBl : sBh;
#pragma unroll
            for (int k16 = 0; k16 < 2; k16++) {
                int kb = tig + k16 * 8;
                uint32_t a[2][4];
#pragma unroll
                for (int fm = 0; fm < 2; fm++) {
                    int base = (wm * 32 + fm * 16 + grp) * ASTR;
                    a[fm][0] = Ap[base + kb];
                    a[fm][1] = Ap[base + 8 * ASTR + kb];
                    a[fm][2] = Ap[base + kb + 4];
                    a[fm][3] = Ap[base + 8 * ASTR + kb + 4];
                }
#pragma unroll
                for (int fn = 0; fn < 4; fn++) {
                    int nb = (wn * 32 + fn * 8 + grp) * ASTR;
                    uint32_t b0 = Bp[nb + kb];
                    uint32_t b1 = Bp[nb + kb + 4];
#pragma unroll
                    for (int fm = 0; fm < 2; fm++)
                        mma16816(c[fm][fn][0], c[fm][fn][1], c[fm][fn][2], c[fm][fn][3],
                                 a[fm][0], a[fm][1], a[fm][2], a[fm][3], b0, b1);
                }
            }
        }
        __syncthreads();
    }

    // epilogue
#pragma unroll
    for (int fm = 0; fm < 2; fm++) {
        int r0 = bm + wm * 32 + fm * 16 + grp;
        int r1 = r0 + 8;
#pragma unroll
        for (int fn = 0; fn < 4; fn++) {
            int col = bn + wn * 32 + fn * 8 + tig * 2;
            float bx = 0.f, by = 0.f;
            if (bias) {
                bx = bias[col];
                by = bias[col + 1];
            }
            if (r0 < M) {
                float vx = c[fm][fn][0] + bx;
                float vy = c[fm][fn][1] + by;
                if (Cin) {
                    float2 old = *(const float2*)(Cin + (size_t)r0 * N + col);
                    vx += old.x;
                    vy += old.y;
                }
                *(float2*)(C + (size_t)r0 * N + col) = make_float2(vx, vy);
            }
            if (r1 < M) {
                float vx = c[fm][fn][2] + bx;
                float vy = c[fm][fn][3] + by;
                if (Cin) {
                    float2 old = *(const float2*)(Cin + (size_t)r1 * N + col);
                    vx += old.x;
                    vy += old.y;
                }
                *(float2*)(C + (size_t)r1 * N + col) = make_float2(vx, vy);
            }
        }
    }
}

// ---------------- GATv2 attention: one warp per dst node, online softmax ----------------
// xlr: [N, 768] combined (xl cols 0..383, xr cols 384..767)
__global__ void attn_kernel(const float* __restrict__ xlr, const float* __restrict__ att,
                            const float* __restrict__ bias, const int* __restrict__ rowptr,
                            const int* __restrict__ srcs, float* __restrict__ out) {
    int w = (blockIdx.x * blockDim.x + threadIdx.x) >> 5;
    if (w >= NN) return;
    int lane = threadIdx.x & 31;
    const float4* xlr4 = (const float4*)xlr;
    const float4* at4 = (const float4*)att;
    const float4* b4 = (const float4*)bias;

    size_t rrb = (size_t)w * 192 + 96 + lane;  // xr base
    float4 r0 = xlr4[rrb], r1 = xlr4[rrb + 32], r2 = xlr4[rrb + 64];
    float4 a0 = at4[lane], a1 = at4[32 + lane], a2 = at4[64 + lane];

    float4 acc0 = make_float4(0, 0, 0, 0), acc1 = acc0, acc2 = acc0;
    float den0 = 0.f, den1 = 0.f, den2 = 0.f;
    float m0 = -1e30f, m1 = -1e30f, m2 = -1e30f;

    int beg = rowptr[w], end = rowptr[w + 1];
    for (int e = beg; e < end; e++) {
        int s = srcs[e];
        const float4* p = xlr4 + (size_t)s * 192 + lane;
        float4 x0 = p[0], x1 = p[32], x2 = p[64];
        float s0 = f4dot(a0, f4lrelu(f4add(x0, r0)));
        float s1 = f4dot(a1, f4lrelu(f4add(x1, r1)));
        float s2 = f4dot(a2, f4lrelu(f4add(x2, r2)));
#pragma unroll
        for (int o = 16; o; o >>= 1) {
            s0 += __shfl_xor_sync(0xffffffffu, s0, o);
            s1 += __shfl_xor_sync(0xffffffffu, s1, o);
            s2 += __shfl_xor_sync(0xffffffffu, s2, o);
        }
        if (s0 > m0) { float cc = __expf(m0 - s0); acc0 = f4scale(acc0, cc); den0 *= cc; m0 = s0; }
        if (s1 > m1) { float cc = __expf(m1 - s1); acc1 = f4scale(acc1, cc); den1 *= cc; m1 = s1; }
        if (s2 > m2) { float cc = __expf(m2 - s2); acc2 = f4scale(acc2, cc); den2 *= cc; m2 = s2; }
        float w0 = __expf(s0 - m0);
        float w1 = __expf(s1 - m1);
        float w2 = __expf(s2 - m2);
        acc0 = f4fma(x0, w0, acc0); den0 += w0;
        acc1 = f4fma(x1, w1, acc1); den1 += w1;
        acc2 = f4fma(x2, w2, acc2); den2 += w2;
    }
    float4* o4 = (float4*)out;
    size_t ob = (size_t)w * 96 + lane;
    o4[ob]      = f4add(f4scale(acc0, 1.0f / den0), b4[lane]);
    o4[ob + 32] = f4add(f4scale(acc1, 1.0f / den1), b4[32 + lane]);
    o4[ob + 64] = f4add(f4scale(acc2, 1.0f / den2), b4[64 + lane]);
}

// ---------------- BatchNorm ----------------
__global__ void bn_zero_kernel(float* s, float* q) {
    int i = threadIdx.x;
    if (i < DH) s[i] = 0.f;
    else if (i < 2 * DH) q[i - DH] = 0.f;
}

__global__ void bn_stats_kernel(const float* __restrict__ x, float* __restrict__ sum,
                                float* __restrict__ sq) {
    int col = threadIdx.x;
    float s = 0.f, q = 0.f;
    for (int r = blockIdx.x; r < NN; r += gridDim.x) {
        float v = x[(size_t)r * DH + col];
        s += v;
        q = fmaf(v, v, q);
    }
    atomicAdd(&sum[col], s);
    atomicAdd(&sq[col], q);
}

__global__ void bn_apply_kernel(const float* __restrict__ x, const float* __restrict__ sum,
                                const float* __restrict__ sq, const float* __restrict__ g,
                                const float* __restrict__ be, float* __restrict__ out) {
    int i = blockIdx.x * blockDim.x + threadIdx.x;
    if (i >= NN * DH) return;
    int col = i & (DH - 1);
    const float invN = 1.0f / (float)NN;
    float mu = sum[col] * invN;
    float var = sq[col] * invN - mu * mu;
    float v = g[col] * (x[i] - mu) * rsqrtf(var + 1e-5f) + be[col];
    out[i] = v > 0.f ? v : 0.f;
}

// ---------------- host ----------------
static void* symaddr(const void* sym) {
    void* p = nullptr;
    cudaGetSymbolAddress(&p, sym);
    return p;
}

extern "C" void kernel_launch(void* const* d_in, const int* in_sizes, int n_in,
                              void* d_out, int out_size) {
    const float* x       = (const float*)d_in[0];
    const int* ei        = (const int*)d_in[1];
    const float* Wl1 = (const float*)d_in[2];
    const float* bl1 = (const float*)d_in[3];
    const float* Wr1 = (const float*)d_in[4];
    const float* br1 = (const float*)d_in[5];
    const float* att1 = (const float*)d_in[6];
    const float* bc1 = (const float*)d_in[7];
    const float* g1 = (const float*)d_in[8];
    const float* be1 = (const float*)d_in[9];
    const float* Wl2 = (const float*)d_in[10];
    const float* bl2 = (const float*)d_in[11];
    const float* Wr2 = (const float*)d_in[12];
    const float* br2 = (const float*)d_in[13];
    const float* att2 = (const float*)d_in[14];
    const float* bc2 = (const float*)d_in[15];
    const float* g2 = (const float*)d_in[16];
    const float* be2 = (const float*)d_in[17];
    const float* W1 = (const float*)d_in[18];
    const float* b1 = (const float*)d_in[19];
    const float* W2 = (const float*)d_in[20];
    const float* b2 = (const float*)d_in[21];
    float* out = (float*)d_out;

    float* xlr   = (float*)symaddr(g_xlr);
    float* xin   = (float*)symaddr(g_xin);
    float* h2    = (float*)symaddr(g_h2);
    float* h     = (float*)symaddr(g_h);
    float* y     = (float*)symaddr(g_y);
    int* deg     = (int*)symaddr(g_deg);
    int* rowptr  = (int*)symaddr(g_rowptr);
    int* fill    = (int*)symaddr(g_fill);
    int* srcs    = (int*)symaddr(g_srcs);
    float* bnsum = (float*)symaddr(g_bnsum);
    float* bnsq  = (float*)symaddr(g_bnsq);
    float* bcat  = (float*)symaddr(g_bcat);
    __nv_bfloat16* sxh = (__nv_bfloat16*)symaddr(g_sxh);
    __nv_bfloat16* sxl = (__nv_bfloat16*)symaddr(g_sxl);
    __nv_bfloat16* sah = (__nv_bfloat16*)symaddr(g_sah);
    __nv_bfloat16* sal = (__nv_bfloat16*)symaddr(g_sal);
    __nv_bfloat16* sch = (__nv_bfloat16*)symaddr(g_sch);
    __nv_bfloat16* scl = (__nv_bfloat16*)symaddr(g_scl);
    __nv_bfloat16* wth = (__nv_bfloat16*)symaddr(g_wth);
    __nv_bfloat16* wtl = (__nv_bfloat16*)symaddr(g_wtl);

    // ---- CSR build ----
    set_int_kernel<<<(NN + 255) / 256, 256>>>(deg, NN, 1);
    hist_kernel<<<(EE + 255) / 256, 256>>>(ei, deg);
    scan_kernel<<<1, 1024>>>(deg, rowptr, fill);
    scatter_kernel<<<(TOTE + 255) / 256, 256>>>(ei, fill, srcs);

    const int MT = (NN + 127) / 128;  // 196
    dim3 gN768(2 * HD / 64, MT);
    dim3 gN128(DH / 64, MT);
    int attn_blocks = (NN * 32 + 255) / 256;
    int wsplit_blocks = (DH * HD + 255) / 256;

    // ---- Layer 1 ----
    split_kernel<<<(NN * DH + 255) / 256, 256>>>(x, sxh, sxl, NN * DH);
    tsplit_kernel<<<wsplit_blocks, 256>>>(Wl1, wth, wtl, DH, HD);
    tsplit_kernel<<<wsplit_blocks, 256>>>(Wr1, wth + (size_t)HD * DH, wtl + (size_t)HD * DH,
                                          DH, HD);
    bcat_kernel<<<3, 256>>>(bl1, br1, bcat);
    gemm_mma_kernel<<<gN768, 256>>>(sxh, sxl, wth, wtl, bcat, nullptr, xlr, NN, 2 * HD, DH);
    attn_kernel<<<attn_blocks, 256>>>(xlr, att1, bc1, rowptr, srcs, xin);
    split_kernel<<<(NN * HD + 255) / 256, 256>>>(xin, sah, sal, NN * HD);
    tsplit_kernel<<<wsplit_blocks, 256>>>(W1, wth, wtl, HD, DH);
    gemm_mma_kernel<<<gN128, 256>>>(sah, sal, wth, wtl, b1, nullptr, y, NN, DH, HD);
    bn_zero_kernel<<<1, 256>>>(bnsum, bnsq);
    bn_stats_kernel<<<256, DH>>>(y, bnsum, bnsq);
    bn_apply_kernel<<<(NN * DH + 255) / 256, 256>>>(y, bnsum, bnsq, g1, be1, h);

    // ---- Layer 2 ----
    split_kernel<<<(NN * DH + 255) / 256, 256>>>(h, sxh, sxl, NN * DH);
    tsplit_kernel<<<wsplit_blocks, 256>>>(Wl2, wth, wtl, DH, HD);
    tsplit_kernel<<<wsplit_blocks, 256>>>(Wr2, wth + (size_t)HD * DH, wtl + (size_t)HD * DH,
                                          DH, HD);
    bcat_kernel<<<3, 256>>>(bl2, br2, bcat);
    gemm_mma_kernel<<<gN768, 256>>>(sxh, sxl, wth, wtl, bcat, nullptr, xlr, NN, 2 * HD, DH);
    attn_kernel<<<attn_blocks, 256>>>(xlr, att2, bc2, rowptr, srcs, h2);
    split_kernel<<<(NN * HD + 255) / 256, 256>>>(h2, sch, scl, NN * HD);
    // y = h2 @ W2[0:384] + b2
    tsplit_kernel<<<wsplit_blocks, 256>>>(W2, wth, wtl, HD, DH);
    gemm_mma_kernel<<<gN128, 256>>>(sch, scl, wth, wtl, b2, nullptr, y, NN, DH, HD);
    // y += xin @ W2[384:768]
    tsplit_kernel<<<wsplit_blocks, 256>>>(W2 + (size_t)HD * DH, wth, wtl, HD, DH);
    gemm_mma_kernel<<<gN128, 256>>>(sah, sal, wth, wtl, nullptr, y, y, NN, DH, HD);
    bn_zero_kernel<<<1, 256>>>(bnsum, bnsq);
    bn_stats_kernel<<<256, DH>>>(y, bnsum, bnsq);
    bn_apply_kernel<<<(NN * DH + 255) / 256, 256>>>(y, bnsum, bnsq, g2, be2, out);
}